// round 16
// baseline (speedup 1.0000x reference)
#include <cuda_runtime.h>
#include <cuda_bf16.h>
#include <cuda_fp16.h>
#include <cstdint>
#include <math.h>

#define T_DIM 2048
#define B_DIM 4
#define E_DIM 512
#define H_DIM 8
#define HD    64
#define BH    (B_DIM*H_DIM)
#define QSCALE 0.1803368801111244f   // 0.125 * log2(e): softmax uses exp2
#define M_ROWS (T_DIM*B_DIM)
#define ATTN_ELEMS (T_DIM*B_DIM*E_DIM)

// ---------------- scratch globals (fp16; hi-only except ctx) ----------------
__device__ __half g_xh[M_ROWS * E_DIM];              // hi only
__device__ __half g_wih[3 * E_DIM * E_DIM];          // hi only
__device__ __half g_woh[E_DIM * E_DIM];              // hi only
__device__ __half g_qh[BH * T_DIM * HD];             // hi only (pre-scaled by QSCALE)
__device__ __half g_kh[BH * T_DIM * HD];             // hi only
__device__ __half g_vth[BH * HD * T_DIM];            // [bh][d][t], hi only
__device__ __half g_ch[M_ROWS * E_DIM];              // ctx hi  [t*B+b][e]
__device__ __half g_cl[M_ROWS * E_DIM];              // ctx lo (out-proj stays 2-pass)
__device__ float g_il[BH * T_DIM];
__device__ __align__(16) __half g_p[(size_t)BH * T_DIM * T_DIM];  // 256MB

// ---------------- helpers ----------------
__device__ __forceinline__ uint32_t smem_u32(const void* p) {
    uint32_t a;
    asm("{ .reg .u64 t; cvta.to.shared.u64 t, %1; cvt.u32.u64 %0, t; }" : "=r"(a) : "l"(p));
    return a;
}

__device__ __forceinline__ float ex2(float x) {
    float r;
    asm("ex2.approx.f32 %0, %1;" : "=f"(r) : "f"(x));
    return r;
}

__device__ __forceinline__ void ldsm4(uint32_t addr, uint32_t* r) {
    asm volatile("ldmatrix.sync.aligned.m8n8.x4.shared.b16 {%0,%1,%2,%3}, [%4];"
                 : "=r"(r[0]), "=r"(r[1]), "=r"(r[2]), "=r"(r[3]) : "r"(addr));
}

__device__ __forceinline__ void mma_h(float* c, const uint32_t* a, const uint32_t* b) {
    asm volatile("mma.sync.aligned.m16n8k16.row.col.f32.f16.f16.f32 "
                 "{%0,%1,%2,%3},{%4,%5,%6,%7},{%8,%9},{%0,%1,%2,%3};"
                 : "+f"(c[0]), "+f"(c[1]), "+f"(c[2]), "+f"(c[3])
                 : "r"(a[0]), "r"(a[1]), "r"(a[2]), "r"(a[3]), "r"(b[0]), "r"(b[1]));
}

__device__ __forceinline__ void cpa16(uint32_t dst, const void* src) {
    asm volatile("cp.async.cg.shared.global [%0], [%1], 16;" :: "r"(dst), "l"(src));
}
#define CP_COMMIT() asm volatile("cp.async.commit_group;" ::: "memory")
#define CP_WAIT1()  asm volatile("cp.async.wait_group 1;" ::: "memory")
#define CP_WAIT2()  asm volatile("cp.async.wait_group 2;" ::: "memory")

// tiles: rows x 64 fp16, row pitch 128B, 16B-chunk XOR swizzle
__device__ __forceinline__ uint32_t addrA(uint32_t base, int m0, int kc, int lane) {
    int g = lane >> 3, r8 = lane & 7;
    int row = m0 + r8 + ((g & 1) << 3);
    int ch  = kc + (g >> 1);
    return base + row * 128 + ((ch ^ (row & 7)) << 4);
}
__device__ __forceinline__ uint32_t addrB(uint32_t base, int n0, int kc, int lane) {
    int g = lane >> 3, r8 = lane & 7;
    int row = n0 + r8 + ((g >> 1) << 3);
    int ch  = kc + (g & 1);
    return base + row * 128 + ((ch ^ (row & 7)) << 4);
}

// fp16 hi/lo pack (used for ctx only)
__device__ __forceinline__ uint32_t packsplit_h(float x, float y, uint32_t* lo) {
    __half2 h2 = __floats2half2_rn(x, y);
    float hx = __low2float(h2), hy = __high2float(h2);
    __half2 l2 = __floats2half2_rn(x - hx, y - hy);
    *lo = *(uint32_t*)&l2;
    return *(uint32_t*)&h2;
}

// ---------------- merged convert kernel ----------------
#define NX  (M_ROWS * E_DIM)
#define NWI (3 * E_DIM * E_DIM)
#define NWO (E_DIM * E_DIM)
__global__ void split_all(const float* __restrict__ x,
                          const float* __restrict__ wi,
                          const float* __restrict__ wo)
{
    int i = blockIdx.x * blockDim.x + threadIdx.x;
    if (i < NX) {
        g_xh[i] = __float2half_rn(x[i]);
    } else if (i < NX + NWI) {
        g_wih[i - NX] = __float2half_rn(wi[i - NX]);
    } else if (i < NX + NWI + NWO) {
        g_woh[i - NX - NWI] = __float2half_rn(wo[i - NX - NWI]);
    }
}

// ---------------- projection GEMM: 128x64 CTA tile ----------------
// TWO_PASS=false (in-proj): A=x hi only, 3-stage pipeline (stage 24576)
// TWO_PASS=true  (out-proj): A=ctx hi/lo, 2-stage pipeline (stage 40960)
template<bool TWO_PASS>
__device__ __forceinline__ void gemm_issue(uint32_t stage_base,
    const __half* Ah, const __half* Al, const __half* Bh,
    int m0, int n0, int ko, int tid)
{
    const uint32_t BHO = TWO_PASS ? 32768u : 16384u;
    #pragma unroll
    for (int i = 0; i < 4; i++) {
        int idx = tid + i * 256;          // 0..1023
        int r = idx >> 3, ch = idx & 7;
        uint32_t off = r * 128 + ((ch ^ (r & 7)) << 4);
        cpa16(stage_base + off, Ah + (size_t)(m0 + r) * E_DIM + ko + ch * 8);
        if (TWO_PASS)
            cpa16(stage_base + 16384 + off, Al + (size_t)(m0 + r) * E_DIM + ko + ch * 8);
    }
    #pragma unroll
    for (int i = 0; i < 2; i++) {
        int idx = tid + i * 256;          // 0..511
        int r = idx >> 3, ch = idx & 7;
        uint32_t off = r * 128 + ((ch ^ (r & 7)) << 4);
        cpa16(stage_base + BHO + off, Bh + (size_t)(n0 + r) * E_DIM + ko + ch * 8);
    }
}

template<bool TWO_PASS>
__global__ __launch_bounds__(256) void gemm_mma(const float* __restrict__ bias,
                                                float* __restrict__ C)
{
    extern __shared__ char smem[];
    const __half* Ah = TWO_PASS ? g_ch : g_xh;
    const __half* Al = TWO_PASS ? g_cl : nullptr;
    const __half* Bh = TWO_PASS ? g_woh : g_wih;
    const uint32_t BHO = TWO_PASS ? 32768u : 16384u;
    const uint32_t STG = TWO_PASS ? 40960u : 24576u;
    const int NS = TWO_PASS ? 2 : 3;

    const uint32_t sb = smem_u32(smem);
    const int tid = threadIdx.x, lane = tid & 31, wid = tid >> 5;
    const int wm0 = (wid & 3) * 32, wn0 = (wid >> 2) * 32;
    const int m0 = blockIdx.y * 128, n0 = blockIdx.x * 64;

    #pragma unroll
    for (int i = 0; i < NS; i++) {
        gemm_issue<TWO_PASS>(sb + i * STG, Ah, Al, Bh, m0, n0, i * 64, tid);
        CP_COMMIT();
    }

    float c[2][4][4] = {};
    for (int s = 0; s < 8; s++) {
        if (TWO_PASS) CP_WAIT1(); else CP_WAIT2();
        __syncthreads();
        uint32_t st = sb + (s % NS) * STG;
        #pragma unroll
        for (int kc = 0; kc < 8; kc += 2) {
            uint32_t ah[2][4], al[2][4], bhf[4][2];
            #pragma unroll
            for (int i = 0; i < 2; i++) {
                ldsm4(addrA(st, wm0 + i * 16, kc, lane), ah[i]);
                if (TWO_PASS)
                    ldsm4(addrA(st + 16384, wm0 + i * 16, kc, lane), al[i]);
            }
            #pragma unroll
            for (int jj = 0; jj < 2; jj++) {
                uint32_t t[4];
                ldsm4(addrB(st + BHO, wn0 + jj * 16, kc, lane), t);
                bhf[jj*2][0] = t[0]; bhf[jj*2][1] = t[1];
                bhf[jj*2+1][0] = t[2]; bhf[jj*2+1][1] = t[3];
            }
            #pragma unroll
            for (int i = 0; i < 2; i++)
                #pragma unroll
                for (int j = 0; j < 4; j++) {
                    mma_h(c[i][j], ah[i], bhf[j]);
                    if (TWO_PASS)
                        mma_h(c[i][j], al[i], bhf[j]);
                }
        }
        __syncthreads();
        if (s + NS < 8)
            gemm_issue<TWO_PASS>(sb + (s % NS) * STG, Ah, Al, Bh, m0, n0, (s + NS) * 64, tid);
        CP_COMMIT();
    }

    #pragma unroll
    for (int i = 0; i < 2; i++)
        #pragma unroll
        for (int j = 0; j < 4; j++)
            #pragma unroll
            for (int e = 0; e < 4; e++) {
                int rg = m0 + wm0 + i * 16 + (lane >> 2) + ((e >> 1) << 3);
                int n  = n0 + wn0 + j * 8 + (lane & 3) * 2 + (e & 1);
                float v = c[i][j][e] + bias[n];
                if (!TWO_PASS) {
                    int t = rg >> 2, bb = rg & 3;
                    int sect = n >> 9, jm = n & 511;
                    int hh = jm >> 6, d = jm & 63;
                    int bh = bb * 8 + hh;
                    if (sect == 2) {
                        g_vth[((size_t)bh * HD + d) * T_DIM + t] = __float2half_rn(v);
                    } else {
                        size_t dst = ((size_t)bh * T_DIM + t) * HD + d;
                        if (sect == 0) g_qh[dst] = __float2half_rn(v * QSCALE);
                        else           g_kh[dst] = __float2half_rn(v);
                    }
                } else {
                    C[(size_t)rg * E_DIM + n] = v;
                }
            }
}

// ---------------- flash attention: q-tile 256, 8 warps, 3-stage KV pipeline ------
// 256 threads (8 warps x 32 q-rows), full k width per warp. KV read once per 256 q.
// smem: QH 0 (32KB), KV stages at 32768 + s*16384 (K +0, V +8192) -> 80KB total
__device__ __forceinline__ void flash_issue_kv(uint32_t buf, int bh, int k0, int tid)
{
    #pragma unroll
    for (int i = 0; i < 2; i++) {
        int idx = tid + i * 256;          // 0..511
        int r = idx >> 3, ch = idx & 7;
        uint32_t off = r * 128 + ((ch ^ (r & 7)) << 4);
        cpa16(buf + off,        g_kh  + ((size_t)bh * T_DIM + k0 + r) * HD + ch * 8);
        cpa16(buf + 8192 + off, g_vth + ((size_t)bh * HD + r) * T_DIM + k0 + ch * 8);
    }
}

__global__ __launch_bounds__(256, 1) void flash_mma()
{
    extern __shared__ char smem[];
    const uint32_t sb = smem_u32(smem);
    const int tid = threadIdx.x, lane = tid & 31, w = tid >> 5;
    const int bh = blockIdx.y, q0 = blockIdx.x * 256;
    const int b = bh >> 3, h = bh & 7;
    const int wq0 = w * 32;

    flash_issue_kv(sb + 32768, bh, 0,   tid); CP_COMMIT();
    flash_issue_kv(sb + 49152, bh, 64,  tid); CP_COMMIT();
    flash_issue_kv(sb + 65536, bh, 128, tid); CP_COMMIT();

    // load Q hi to smem (256 rows x 64)
    {
        const __half* Qh = g_qh + ((size_t)bh * T_DIM + q0) * HD;
        #pragma unroll
        for (int i = 0; i < 8; i++) {
            int idx = tid + i * 256;      // 0..2047
            int r = idx >> 3, ch = idx & 7;
            uint32_t off = r * 128 + ((ch ^ (r & 7)) << 4);
            *(uint4*)(smem + off) = *(const uint4*)(Qh + (size_t)r * HD + ch * 8);
        }
    }
    __syncthreads();

    // cache Q fragments in registers (32 rows x 64 k per warp)
    uint32_t qh[2][4][4];
    #pragma unroll
    for (int i = 0; i < 2; i++)
        #pragma unroll
        for (int kk = 0; kk < 4; kk++)
            ldsm4(addrA(sb, wq0 + i * 16, 2 * kk, lane), qh[i][kk]);

    float o[2][8][4] = {};
    float rs[4] = {};

    for (int kt = 0; kt < T_DIM / 64; kt++) {
        CP_WAIT2();
        __syncthreads();
        const uint32_t buf = sb + 32768 + (kt % 3) * 16384;

        // S = Q K^T  (32 x 64 per warp, 1-pass)
        float s[2][8][4] = {};
        #pragma unroll
        for (int kk = 0; kk < 4; kk++)
            #pragma unroll
            for (int jj = 0; jj < 4; jj++) {
                uint32_t th[4];
                ldsm4(addrB(buf, jj * 16, 2 * kk, lane), th);
                uint32_t bh0[2] = {th[0], th[1]}, bh1[2] = {th[2], th[3]};
                #pragma unroll
                for (int i = 0; i < 2; i++) {
                    mma_h(s[i][jj*2], qh[i][kk], bh0);
                    mma_h(s[i][jj*2+1], qh[i][kk], bh1);
                }
            }

        // exp2 (MUFU only) + row sums + pack P hi (fp16) + stream to gmem
        uint32_t aP[2][4][4];
        #pragma unroll
        for (int i = 0; i < 2; i++)
            #pragma unroll
            for (int j = 0; j < 8; j++) {
                float p0 = ex2(s[i][j][0]), p1 = ex2(s[i][j][1]);
                float p2 = ex2(s[i][j][2]), p3 = ex2(s[i][j][3]);
                rs[i*2]   += p0 + p1;
                rs[i*2+1] += p2 + p3;
                __half2 h01 = __floats2half2_rn(p0, p1);
                __half2 h23 = __floats2half2_rn(p2, p3);
                int col = kt * 64 + j * 8 + (lane & 3) * 2;
                int r0 = q0 + wq0 + i * 16 + (lane >> 2);
                __stcs((__half2*)(g_p + ((size_t)bh * T_DIM + r0) * T_DIM + col), h01);
                __stcs((__half2*)(g_p + ((size_t)bh * T_DIM + r0 + 8) * T_DIM + col), h23);
                int kk = j >> 1, m = (j & 1) * 2;
                aP[i][kk][m]   = *(uint32_t*)&h01;
                aP[i][kk][m+1] = *(uint32_t*)&h23;
            }

        // O += P V  (B = Vt hi in smem, 1-pass)
        #pragma unroll
        for (int kk = 0; kk < 4; kk++)
            #pragma unroll
            for (int jj = 0; jj < 4; jj++) {
                uint32_t th[4];
                ldsm4(addrB(buf + 8192, jj * 16, 2 * kk, lane), th);
                uint32_t bh0[2] = {th[0], th[1]}, bh1[2] = {th[2], th[3]};
                #pragma unroll
                for (int i = 0; i < 2; i++) {
                    mma_h(o[i][jj*2], aP[i][kk], bh0);
                    mma_h(o[i][jj*2+1], aP[i][kk], bh1);
                }
            }
        __syncthreads();
        if (kt + 3 < T_DIM / 64)
            flash_issue_kv(sb + 32768 + (kt % 3) * 16384, bh, (kt + 3) * 64, tid);
        CP_COMMIT();
    }

    // quad-reduce row sums
    #pragma unroll
    for (int x = 0; x < 4; x++) {
        rs[x] += __shfl_xor_sync(0xffffffffu, rs[x], 1);
        rs[x] += __shfl_xor_sync(0xffffffffu, rs[x], 2);
    }
    float il[4] = {1.0f / rs[0], 1.0f / rs[1], 1.0f / rs[2], 1.0f / rs[3]};

    // write ctx (fp16 hi/lo) and 1/l
    #pragma unroll
    for (int i = 0; i < 2; i++)
        #pragma unroll
        for (int hf = 0; hf < 2; hf++) {
            int r = wq0 + i * 16 + (lane >> 2) + hf * 8;
            float s_il = il[i*2 + hf];
            #pragma unroll
            for (int j = 0; j < 8; j++) {
                int cc = j * 8 + (lane & 3) * 2;
                uint32_t lo;
                uint32_t hi = packsplit_h(o[i][j][hf*2] * s_il, o[i][j][hf*2+1] * s_il, &lo);
                size_t off = ((size_t)(q0 + r) * B_DIM + b) * E_DIM + h * HD + cc;
                *(uint32_t*)&g_ch[off] = hi;
                *(uint32_t*)&g_cl[off] = lo;
            }
            if ((lane & 3) == 0)
                g_il[(size_t)bh * T_DIM + q0 + r] = s_il;
        }
}

// ---------------- avg_weights: pure memory pass over stored P ----------------
__global__ __launch_bounds__(256) void avg_sum(float* __restrict__ outAvg)
{
    const int blk = blockIdx.x;
    const int b = blk >> 11, q = blk & 2047;
    const int tid = threadIdx.x;

    float acc[8] = {};
    #pragma unroll
    for (int hh = 0; hh < H_DIM; hh++) {
        const int bh = b * 8 + hh;
        float il = g_il[(size_t)bh * T_DIM + q] * 0.125f;
        uint4 u = *((const uint4*)(g_p + ((size_t)bh * T_DIM + q) * T_DIM) + tid);
        __half2* hp = (__half2*)&u;
        #pragma unroll
        for (int c = 0; c < 4; c++) {
            float2 f = __half22float2(hp[c]);
            acc[c*2]   = fmaf(f.x, il, acc[c*2]);
            acc[c*2+1] = fmaf(f.y, il, acc[c*2+1]);
        }
    }
    float* dst = outAvg + ((size_t)b * T_DIM + q) * T_DIM + tid * 8;
    *(float4*)dst       = make_float4(acc[0], acc[1], acc[2], acc[3]);
    *(float4*)(dst + 4) = make_float4(acc[4], acc[5], acc[6], acc[7]);
}

// ---------------- launch ----------------
extern "C" void kernel_launch(void* const* d_in, const int* in_sizes, int n_in,
                              void* d_out, int out_size)
{
    const float* x     = (const float*)d_in[0];
    const float* w_in  = (const float*)d_in[1];
    const float* b_in  = (const float*)d_in[2];
    const float* w_out = (const float*)d_in[3];
    const float* b_out = (const float*)d_in[4];
    float* out = (float*)d_out;

    static cudaStream_t s2 = nullptr;
    static cudaEvent_t ev1 = nullptr, ev2 = nullptr;
    if (!s2) {
        cudaStreamCreateWithFlags(&s2, cudaStreamNonBlocking);
        cudaEventCreateWithFlags(&ev1, cudaEventDisableTiming);
        cudaEventCreateWithFlags(&ev2, cudaEventDisableTiming);
    }

    split_all<<<(NX + NWI + NWO + 255) / 256, 256>>>(x, w_in, w_out);

    cudaFuncSetAttribute(gemm_mma<false>, cudaFuncAttributeMaxDynamicSharedMemorySize, 73728);
    cudaFuncSetAttribute(gemm_mma<true>,  cudaFuncAttributeMaxDynamicSharedMemorySize, 81920);
    gemm_mma<false><<<dim3(3 * E_DIM / 64, M_ROWS / 128), 256, 73728>>>(b_in, out);

    cudaFuncSetAttribute(flash_mma, cudaFuncAttributeMaxDynamicSharedMemorySize, 81920);
    flash_mma<<<dim3(T_DIM / 256, BH), 256, 81920>>>();

    // fork: avg_sum (DRAM-bound) runs concurrently with out-proj gemm (tensor-bound)
    cudaEventRecord(ev1, 0);
    cudaStreamWaitEvent(s2, ev1, 0);
    avg_sum<<<B_DIM * T_DIM, 256, 0, s2>>>(out + ATTN_ELEMS);
    cudaEventRecord(ev2, s2);

    gemm_mma<true><<<dim3(E_DIM / 64, M_ROWS / 128), 256, 81920>>>(b_out, out);

    cudaStreamWaitEvent(0, ev2, 0);
}

// round 17
// speedup vs baseline: 1.1348x; 1.1348x over previous
#include <cuda_runtime.h>
#include <cuda_bf16.h>
#include <cuda_fp16.h>
#include <cstdint>
#include <math.h>

#define T_DIM 2048
#define B_DIM 4
#define E_DIM 512
#define H_DIM 8
#define HD    64
#define BH    (B_DIM*H_DIM)
#define QSCALE 0.1803368801111244f   // 0.125 * log2(e): softmax uses exp2
#define M_ROWS (T_DIM*B_DIM)
#define ATTN_ELEMS (T_DIM*B_DIM*E_DIM)

// ---------------- scratch globals (fp16, hi-only everywhere) ----------------
__device__ __half g_xh[M_ROWS * E_DIM];
__device__ __half g_wih[3 * E_DIM * E_DIM];
__device__ __half g_woh[E_DIM * E_DIM];
__device__ __half g_qh[BH * T_DIM * HD];             // pre-scaled by QSCALE
__device__ __half g_kh[BH * T_DIM * HD];
__device__ __half g_vth[BH * HD * T_DIM];            // [bh][d][t]
__device__ __half g_ch[M_ROWS * E_DIM];              // ctx [t*B+b][e]
__device__ float g_il[BH * T_DIM];
__device__ __align__(16) __half g_p[(size_t)BH * T_DIM * T_DIM];  // 256MB

// ---------------- helpers ----------------
__device__ __forceinline__ uint32_t smem_u32(const void* p) {
    uint32_t a;
    asm("{ .reg .u64 t; cvta.to.shared.u64 t, %1; cvt.u32.u64 %0, t; }" : "=r"(a) : "l"(p));
    return a;
}

__device__ __forceinline__ float ex2(float x) {
    float r;
    asm("ex2.approx.f32 %0, %1;" : "=f"(r) : "f"(x));
    return r;
}

__device__ __forceinline__ void ldsm4(uint32_t addr, uint32_t* r) {
    asm volatile("ldmatrix.sync.aligned.m8n8.x4.shared.b16 {%0,%1,%2,%3}, [%4];"
                 : "=r"(r[0]), "=r"(r[1]), "=r"(r[2]), "=r"(r[3]) : "r"(addr));
}

__device__ __forceinline__ void mma_h(float* c, const uint32_t* a, const uint32_t* b) {
    asm volatile("mma.sync.aligned.m16n8k16.row.col.f32.f16.f16.f32 "
                 "{%0,%1,%2,%3},{%4,%5,%6,%7},{%8,%9},{%0,%1,%2,%3};"
                 : "+f"(c[0]), "+f"(c[1]), "+f"(c[2]), "+f"(c[3])
                 : "r"(a[0]), "r"(a[1]), "r"(a[2]), "r"(a[3]), "r"(b[0]), "r"(b[1]));
}

__device__ __forceinline__ void cpa16(uint32_t dst, const void* src) {
    asm volatile("cp.async.cg.shared.global [%0], [%1], 16;" :: "r"(dst), "l"(src));
}
#define CP_COMMIT() asm volatile("cp.async.commit_group;" ::: "memory")
#define CP_WAIT1()  asm volatile("cp.async.wait_group 1;" ::: "memory")

// tiles: rows x 64 fp16, row pitch 128B, 16B-chunk XOR swizzle
__device__ __forceinline__ uint32_t addrA(uint32_t base, int m0, int kc, int lane) {
    int g = lane >> 3, r8 = lane & 7;
    int row = m0 + r8 + ((g & 1) << 3);
    int ch  = kc + (g >> 1);
    return base + row * 128 + ((ch ^ (row & 7)) << 4);
}
__device__ __forceinline__ uint32_t addrB(uint32_t base, int n0, int kc, int lane) {
    int g = lane >> 3, r8 = lane & 7;
    int row = n0 + r8 + ((g >> 1) << 3);
    int ch  = kc + (g & 1);
    return base + row * 128 + ((ch ^ (row & 7)) << 4);
}

// ---------------- merged convert kernel ----------------
#define NX  (M_ROWS * E_DIM)
#define NWI (3 * E_DIM * E_DIM)
#define NWO (E_DIM * E_DIM)
__global__ void split_all(const float* __restrict__ x,
                          const float* __restrict__ wi,
                          const float* __restrict__ wo)
{
    int i = blockIdx.x * blockDim.x + threadIdx.x;
    if (i < NX) {
        g_xh[i] = __float2half_rn(x[i]);
    } else if (i < NX + NWI) {
        g_wih[i - NX] = __float2half_rn(wi[i - NX]);
    } else if (i < NX + NWI + NWO) {
        g_woh[i - NX - NWI] = __float2half_rn(wo[i - NX - NWI]);
    }
}

// ---------------- projection GEMM: 128x64 CTA tile, 1-pass fp16, 2-stage ---------
// MODE 0 = in-proj (A=x, B=w_in, scatter epilogue); MODE 1 = out-proj (A=ctx, C store)
// stage layout: AH 0 (16KB), BH 16384 (8KB); stage size 24576, 2 stages = 48KB
template<int MODE>
__device__ __forceinline__ void gemm_issue(uint32_t stage_base,
    const __half* Ah, const __half* Bh, int m0, int n0, int ko, int tid)
{
    #pragma unroll
    for (int i = 0; i < 4; i++) {
        int idx = tid + i * 256;          // 0..1023
        int r = idx >> 3, ch = idx & 7;
        uint32_t off = r * 128 + ((ch ^ (r & 7)) << 4);
        cpa16(stage_base + off, Ah + (size_t)(m0 + r) * E_DIM + ko + ch * 8);
    }
    #pragma unroll
    for (int i = 0; i < 2; i++) {
        int idx = tid + i * 256;          // 0..511
        int r = idx >> 3, ch = idx & 7;
        uint32_t off = r * 128 + ((ch ^ (r & 7)) << 4);
        cpa16(stage_base + 16384 + off, Bh + (size_t)(n0 + r) * E_DIM + ko + ch * 8);
    }
}

template<int MODE>
__global__ __launch_bounds__(256) void gemm_mma(const float* __restrict__ bias,
                                                float* __restrict__ C)
{
    extern __shared__ char smem[];
    const __half* Ah = (MODE == 1) ? g_ch : g_xh;
    const __half* Bh = (MODE == 1) ? g_woh : g_wih;

    const uint32_t sb = smem_u32(smem);
    const int tid = threadIdx.x, lane = tid & 31, wid = tid >> 5;
    const int wm0 = (wid & 3) * 32, wn0 = (wid >> 2) * 32;
    const int m0 = blockIdx.y * 128, n0 = blockIdx.x * 64;

    gemm_issue<MODE>(sb,         Ah, Bh, m0, n0, 0,  tid); CP_COMMIT();
    gemm_issue<MODE>(sb + 24576, Ah, Bh, m0, n0, 64, tid); CP_COMMIT();

    float c[2][4][4] = {};
    for (int s = 0; s < 8; s++) {
        CP_WAIT1();
        __syncthreads();
        uint32_t st = sb + (s & 1) * 24576;
        #pragma unroll
        for (int kc = 0; kc < 8; kc += 2) {
            uint32_t ah[2][4], bhf[4][2];
            #pragma unroll
            for (int i = 0; i < 2; i++)
                ldsm4(addrA(st, wm0 + i * 16, kc, lane), ah[i]);
            #pragma unroll
            for (int jj = 0; jj < 2; jj++) {
                uint32_t t[4];
                ldsm4(addrB(st + 16384, wn0 + jj * 16, kc, lane), t);
                bhf[jj*2][0] = t[0]; bhf[jj*2][1] = t[1];
                bhf[jj*2+1][0] = t[2]; bhf[jj*2+1][1] = t[3];
            }
            #pragma unroll
            for (int i = 0; i < 2; i++)
                #pragma unroll
                for (int j = 0; j < 4; j++)
                    mma_h(c[i][j], ah[i], bhf[j]);
        }
        __syncthreads();
        if (s + 2 < 8)
            gemm_issue<MODE>(sb + (s & 1) * 24576, Ah, Bh, m0, n0, (s + 2) * 64, tid);
        CP_COMMIT();
    }

    #pragma unroll
    for (int i = 0; i < 2; i++)
        #pragma unroll
        for (int j = 0; j < 4; j++)
            #pragma unroll
            for (int hf = 0; hf < 2; hf++) {
                int rg = m0 + wm0 + i * 16 + (lane >> 2) + hf * 8;
                int n  = n0 + wn0 + j * 8 + (lane & 3) * 2;
                float v0 = c[i][j][hf*2]   + bias[n];
                float v1 = c[i][j][hf*2+1] + bias[n+1];
                if (MODE == 0) {
                    int t = rg >> 2, bb = rg & 3;
                    int sect = n >> 9, jm = n & 511;
                    int hh = jm >> 6, d = jm & 63;     // d even, d+1 same head
                    int bh = bb * 8 + hh;
                    if (sect == 2) {
                        size_t dst = ((size_t)bh * HD + d) * T_DIM + t;
                        g_vth[dst]         = __float2half_rn(v0);
                        g_vth[dst + T_DIM] = __float2half_rn(v1);
                    } else {
                        size_t dst = ((size_t)bh * T_DIM + t) * HD + d;
                        if (sect == 0) { v0 *= QSCALE; v1 *= QSCALE; }
                        __half2 hv = __floats2half2_rn(v0, v1);
                        *(__half2*)((sect == 0 ? g_qh : g_kh) + dst) = hv;
                    }
                } else {
                    *(float2*)(C + (size_t)rg * E_DIM + n) = make_float2(v0, v1);
                }
            }
}

// ---------------- flash attention: q-tile 256, smem-staged coalesced P store -----
// 256 threads (8 warps x 32 q-rows). smem: QH 0 (32KB), KV0 32768, KV1 49152,
// P stage 65536 (256 rows x 144B padded = 36864) -> total 102400
#define P_OFF   65536
#define P_PITCH 144
__device__ __forceinline__ void flash_issue_kv(uint32_t buf, int bh, int k0, int tid)
{
    #pragma unroll
    for (int i = 0; i < 2; i++) {
        int idx = tid + i * 256;          // 0..511
        int r = idx >> 3, ch = idx & 7;
        uint32_t off = r * 128 + ((ch ^ (r & 7)) << 4);
        cpa16(buf + off,        g_kh  + ((size_t)bh * T_DIM + k0 + r) * HD + ch * 8);
        cpa16(buf + 8192 + off, g_vth + ((size_t)bh * HD + r) * T_DIM + k0 + ch * 8);
    }
}

__global__ __launch_bounds__(256, 1) void flash_mma()
{
    extern __shared__ char smem[];
    const uint32_t sb = smem_u32(smem);
    const int tid = threadIdx.x, lane = tid & 31, w = tid >> 5;
    const int bh = blockIdx.y, q0 = blockIdx.x * 256;
    const int b = bh >> 3, h = bh & 7;
    const int wq0 = w * 32;

    flash_issue_kv(sb + 32768, bh, 0, tid);  CP_COMMIT();
    flash_issue_kv(sb + 49152, bh, 64, tid); CP_COMMIT();

    // load Q to smem (256 rows x 64)
    {
        const __half* Qh = g_qh + ((size_t)bh * T_DIM + q0) * HD;
        #pragma unroll
        for (int i = 0; i < 8; i++) {
            int idx = tid + i * 256;      // 0..2047
            int r = idx >> 3, ch = idx & 7;
            uint32_t off = r * 128 + ((ch ^ (r & 7)) << 4);
            *(uint4*)(smem + off) = *(const uint4*)(Qh + (size_t)r * HD + ch * 8);
        }
    }
    __syncthreads();

    // cache Q fragments in registers (32 rows x 64 k per warp)
    uint32_t qh[2][4][4];
    #pragma unroll
    for (int i = 0; i < 2; i++)
        #pragma unroll
        for (int kk = 0; kk < 4; kk++)
            ldsm4(addrA(sb, wq0 + i * 16, 2 * kk, lane), qh[i][kk]);

    float o[2][8][4] = {};
    float rs[4] = {};

    for (int kt = 0; kt < T_DIM / 64; kt++) {
        CP_WAIT1();
        __syncthreads();
        const uint32_t buf = sb + 32768 + (kt & 1) * 16384;

        // S = Q K^T  (32 x 64 per warp, 1-pass)
        float s[2][8][4] = {};
        #pragma unroll
        for (int kk = 0; kk < 4; kk++)
            #pragma unroll
            for (int jj = 0; jj < 4; jj++) {
                uint32_t th[4];
                ldsm4(addrB(buf, jj * 16, 2 * kk, lane), th);
                uint32_t bh0[2] = {th[0], th[1]}, bh1[2] = {th[2], th[3]};
                #pragma unroll
                for (int i = 0; i < 2; i++) {
                    mma_h(s[i][jj*2], qh[i][kk], bh0);
                    mma_h(s[i][jj*2+1], qh[i][kk], bh1);
                }
            }

        // exp2 + row sums + pack P (fp16) into smem stage + A-frags
        uint32_t aP[2][4][4];
        #pragma unroll
        for (int i = 0; i < 2; i++)
            #pragma unroll
            for (int j = 0; j < 8; j++) {
                float p0 = ex2(s[i][j][0]), p1 = ex2(s[i][j][1]);
                float p2 = ex2(s[i][j][2]), p3 = ex2(s[i][j][3]);
                rs[i*2]   += p0 + p1;
                rs[i*2+1] += p2 + p3;
                __half2 h01 = __floats2half2_rn(p0, p1);
                __half2 h23 = __floats2half2_rn(p2, p3);
                int srow = wq0 + i * 16 + (lane >> 2);
                uint32_t pa = sb + P_OFF + srow * P_PITCH + j * 16 + (lane & 3) * 4;
                *(__half2*)(smem + (pa - sb))              = h01;
                *(__half2*)(smem + (pa - sb) + 8 * P_PITCH) = h23;
                int kk = j >> 1, m = (j & 1) * 2;
                aP[i][kk][m]   = *(uint32_t*)&h01;
                aP[i][kk][m+1] = *(uint32_t*)&h23;
            }

        // O += P V  (1-pass)
        #pragma unroll
        for (int kk = 0; kk < 4; kk++)
            #pragma unroll
            for (int jj = 0; jj < 4; jj++) {
                uint32_t th[4];
                ldsm4(addrB(buf + 8192, jj * 16, 2 * kk, lane), th);
                uint32_t bh0[2] = {th[0], th[1]}, bh1[2] = {th[2], th[3]};
                #pragma unroll
                for (int i = 0; i < 2; i++) {
                    mma_h(o[i][jj*2], aP[i][kk], bh0);
                    mma_h(o[i][jj*2+1], aP[i][kk], bh1);
                }
            }
        __syncthreads();   // pack complete across CTA; also guards KV slot reuse

        // coalesced P drain: warp w covers rows [w*32, w*32+32), 128B per row store
        {
            size_t grow = (size_t)bh * T_DIM + q0 + w * 32;
            uint32_t prow = sb + P_OFF + (w * 32) * P_PITCH + lane * 4;
            #pragma unroll
            for (int r = 0; r < 32; r++) {
                uint32_t v;
                asm volatile("ld.shared.b32 %0, [%1];" : "=r"(v) : "r"(prow + r * P_PITCH));
                __stcs((uint32_t*)(g_p + (grow + r) * T_DIM + kt * 64) + lane, v);
            }
        }
        if (kt + 2 < T_DIM / 64)
            flash_issue_kv(sb + 32768 + (kt & 1) * 16384, bh, (kt + 2) * 64, tid);
        CP_COMMIT();
    }

    // quad-reduce row sums
    #pragma unroll
    for (int x = 0; x < 4; x++) {
        rs[x] += __shfl_xor_sync(0xffffffffu, rs[x], 1);
        rs[x] += __shfl_xor_sync(0xffffffffu, rs[x], 2);
    }
    float il[4] = {1.0f / rs[0], 1.0f / rs[1], 1.0f / rs[2], 1.0f / rs[3]};

    // write ctx (fp16 hi-only) and 1/l
    #pragma unroll
    for (int i = 0; i < 2; i++)
        #pragma unroll
        for (int hf = 0; hf < 2; hf++) {
            int r = wq0 + i * 16 + (lane >> 2) + hf * 8;
            float s_il = il[i*2 + hf];
            #pragma unroll
            for (int j = 0; j < 8; j++) {
                int cc = j * 8 + (lane & 3) * 2;
                __half2 hv = __floats2half2_rn(o[i][j][hf*2] * s_il, o[i][j][hf*2+1] * s_il);
                size_t off = ((size_t)(q0 + r) * B_DIM + b) * E_DIM + h * HD + cc;
                *(__half2*)&g_ch[off] = hv;
            }
            if ((lane & 3) == 0)
                g_il[(size_t)bh * T_DIM + q0 + r] = s_il;
        }
}

// ---------------- avg_weights: pure memory pass over stored P ----------------
__global__ __launch_bounds__(256) void avg_sum(float* __restrict__ outAvg)
{
    const int blk = blockIdx.x;
    const int b = blk >> 11, q = blk & 2047;
    const int tid = threadIdx.x;

    float acc[8] = {};
    #pragma unroll
    for (int hh = 0; hh < H_DIM; hh++) {
        const int bh = b * 8 + hh;
        float il = g_il[(size_t)bh * T_DIM + q] * 0.125f;
        uint4 u = *((const uint4*)(g_p + ((size_t)bh * T_DIM + q) * T_DIM) + tid);
        __half2* hp = (__half2*)&u;
        #pragma unroll
        for (int c = 0; c < 4; c++) {
            float2 f = __half22float2(hp[c]);
            acc[c*2]   = fmaf(f.x, il, acc[c*2]);
            acc[c*2+1] = fmaf(f.y, il, acc[c*2+1]);
        }
    }
    float* dst = outAvg + ((size_t)b * T_DIM + q) * T_DIM + tid * 8;
    *(float4*)dst       = make_float4(acc[0], acc[1], acc[2], acc[3]);
    *(float4*)(dst + 4) = make_float4(acc[4], acc[5], acc[6], acc[7]);
}

// ---------------- launch ----------------
extern "C" void kernel_launch(void* const* d_in, const int* in_sizes, int n_in,
                              void* d_out, int out_size)
{
    const float* x     = (const float*)d_in[0];
    const float* w_in  = (const float*)d_in[1];
    const float* b_in  = (const float*)d_in[2];
    const float* w_out = (const float*)d_in[3];
    const float* b_out = (const float*)d_in[4];
    float* out = (float*)d_out;

    static cudaStream_t s2 = nullptr;
    static cudaEvent_t ev1 = nullptr, ev2 = nullptr;
    if (!s2) {
        cudaStreamCreateWithFlags(&s2, cudaStreamNonBlocking);
        cudaEventCreateWithFlags(&ev1, cudaEventDisableTiming);
        cudaEventCreateWithFlags(&ev2, cudaEventDisableTiming);
    }

    split_all<<<(NX + NWI + NWO + 255) / 256, 256>>>(x, w_in, w_out);

    cudaFuncSetAttribute(gemm_mma<0>, cudaFuncAttributeMaxDynamicSharedMemorySize, 49152);
    cudaFuncSetAttribute(gemm_mma<1>, cudaFuncAttributeMaxDynamicSharedMemorySize, 49152);
    gemm_mma<0><<<dim3(3 * E_DIM / 64, M_ROWS / 128), 256, 49152>>>(b_in, out);

    cudaFuncSetAttribute(flash_mma, cudaFuncAttributeMaxDynamicSharedMemorySize, 102400);
    flash_mma<<<dim3(T_DIM / 256, BH), 256, 102400>>>();

    // fork: avg_sum (DRAM-bound) runs concurrently with out-proj gemm (tensor-bound)
    cudaEventRecord(ev1, 0);
    cudaStreamWaitEvent(s2, ev1, 0);
    avg_sum<<<B_DIM * T_DIM, 256, 0, s2>>>(out + ATTN_ELEMS);
    cudaEventRecord(ev2, s2);

    gemm_mma<1><<<dim3(E_DIM / 64, M_ROWS / 128), 256, 49152>>>(b_out, out);

    cudaStreamWaitEvent(0, ev2, 0);
}